// round 1
// baseline (speedup 1.0000x reference)
#include <cuda_runtime.h>
#include <math.h>

// ---------------- scratch (static device arrays; no allocation) ----------------
static __device__ float g_y66[8 * 512 * 66 * 66];   // conv output, 71.4 MB
static __device__ float g_partials[2048];
static __device__ float g_inv[1];                   // rsqrt(w_avg_new)
static __device__ float g_styles[8 * 512];
static __device__ float g_mult[8 * 512];            // styles * inv
static __device__ float g_S[512 * 512];             // sum_k conv_w^2
static __device__ float g_demod[8 * 512];

// ---------------- K1a: partial sum of x^2 (deterministic partition) ----------------
__global__ void __launch_bounds__(256) k_reduce(const float* __restrict__ x, int n) {
    float s = 0.f;
    for (int i = blockIdx.x * blockDim.x + threadIdx.x; i < n; i += gridDim.x * blockDim.x) {
        float v = x[i];
        s += v * v;
    }
    __shared__ float sm[256];
    sm[threadIdx.x] = s;
    __syncthreads();
    for (int o = 128; o > 0; o >>= 1) {
        if (threadIdx.x < o) sm[threadIdx.x] += sm[threadIdx.x + o];
        __syncthreads();
    }
    if (threadIdx.x == 0) g_partials[blockIdx.x] = sm[0];
}

// ---------------- K1b: finalize magnitude EMA -> inv scale ----------------
__global__ void __launch_bounds__(1024) k_finalize(const float* __restrict__ w_avg, float inv_n) {
    __shared__ float sm[1024];
    float s = 0.f;
    for (int i = threadIdx.x; i < 2048; i += 1024) s += g_partials[i];
    sm[threadIdx.x] = s;
    __syncthreads();
    for (int o = 512; o > 0; o >>= 1) {
        if (threadIdx.x < o) sm[threadIdx.x] += sm[threadIdx.x + o];
        __syncthreads();
    }
    if (threadIdx.x == 0) {
        float mag = sm[0] * inv_n;
        float wn  = mag + 0.999f * (w_avg[0] - mag);
        g_inv[0]  = rsqrtf(wn);
    }
}

// ---------------- K2: styles = w @ (affine_w/sqrt(512))^T + affine_b ----------------
__global__ void __launch_bounds__(256) k_styles(const float* __restrict__ w,
                                                const float* __restrict__ aw,
                                                const float* __restrict__ ab) {
    int idx = blockIdx.x * 256 + threadIdx.x;  // 4096 = 8*512
    int b = idx >> 9, i = idx & 511;
    const float* wr = w + b * 512;
    const float* ar = aw + i * 512;
    float s = 0.f;
    for (int j = 0; j < 512; j++) s += wr[j] * ar[j];
    s = s * 0.04419417382415922f + ab[i];  // 1/sqrt(512)
    g_styles[idx] = s;
    g_mult[idx]   = s * g_inv[0];
}

// ---------------- K3: S[o][i] = sum_{kh,kw} conv_w^2 ----------------
__global__ void __launch_bounds__(256) k_S(const float* __restrict__ cw) {
    int idx = blockIdx.x * 256 + threadIdx.x;  // 262144 = 512*512
    const float* p = cw + (size_t)idx * 9;
    float s = 0.f;
#pragma unroll
    for (int k = 0; k < 9; k++) s += p[k] * p[k];
    g_S[idx] = s;
}

// ---------------- K4: demod d[b][o] = rsqrt(sum_i styles^2 * S[o][i] + 1e-8) ----------------
__global__ void __launch_bounds__(256) k_demod() {
    int idx = blockIdx.x * 256 + threadIdx.x;  // 4096
    int b = idx >> 9, o = idx & 511;
    const float* st = g_styles + b * 512;
    const float* Sr = g_S + o * 512;
    float s = 0.f;
    for (int i = 0; i < 512; i++) {
        float t = st[i];
        s += t * t * Sr[i];
    }
    g_demod[idx] = rsqrtf(s + 1e-8f);
}

// ---------------- K6: conv 3x3 pad2, shared weights, x scaled per-channel by g_mult ----------------
// Implicit GEMM per batch: M = 66*66 = 4356 flattened pixels, N = 512 oc, K = 512 ic * 9.
// Block tile: 128 M x 64 N, 256 threads, thread = 8M x 4N.
__global__ void __launch_bounds__(256) k_conv(const float* __restrict__ x,
                                              const float* __restrict__ cw,
                                              const float* __restrict__ cb) {
    const int mblk = blockIdx.x, nblk = blockIdx.y, b = blockIdx.z;
    const int tid = threadIdx.x;
    const int tn = tid & 15;   // 16 groups * 4 oc
    const int tm = tid >> 4;   // 16 groups * 8 m
    const int m0 = mblk * 128;
    const int row0 = m0 / 66;

    __shared__ float xs[5][68];   // input rows row0-2 .. row0+2 (pixel coords), cols -2..65
    __shared__ float ws[9][64];   // transposed weights [pos][oc]

    const int mbase = m0 + tm * 8;
    int rr[8], qq[8];
#pragma unroll
    for (int i = 0; i < 8; i++) {
        int m = mbase + i;
        rr[i] = m / 66 - row0;   // 0..2
        qq[i] = m % 66;
    }

    float acc[8][4];
#pragma unroll
    for (int i = 0; i < 8; i++)
#pragma unroll
        for (int j = 0; j < 4; j++) acc[i][j] = 0.f;

    const float* xb = x + (size_t)b * 512 * 4096;
    const float* mb = g_mult + b * 512;

    for (int ic = 0; ic < 512; ++ic) {
        const float mlt = __ldg(mb + ic);
        // load x tile: 5 rows x 68 cols, global row = row0+sr-2, col = c-2
        for (int idx = tid; idx < 340; idx += 256) {
            int sr = idx / 68, c = idx % 68;
            int gr = row0 + sr - 2, gc = c - 2;
            float v = 0.f;
            if ((unsigned)gr < 64u && (unsigned)gc < 64u)
                v = xb[ic * 4096 + gr * 64 + gc] * mlt;
            xs[sr][c] = v;
        }
        // load weights: 64 oc x 9 taps, transposed
        for (int idx = tid; idx < 576; idx += 256) {
            int oc = idx / 9, pos = idx % 9;
            ws[pos][oc] = cw[((size_t)(nblk * 64 + oc) * 512 + ic) * 9 + pos];
        }
        __syncthreads();
#pragma unroll
        for (int pos = 0; pos < 9; ++pos) {
            const int kh = pos / 3, kw = pos % 3;
            float wv[4];
#pragma unroll
            for (int j = 0; j < 4; j++) wv[j] = ws[pos][tn * 4 + j];
#pragma unroll
            for (int i = 0; i < 8; i++) {
                float xv = xs[rr[i] + kh][qq[i] + kw];
#pragma unroll
                for (int j = 0; j < 4; j++) acc[i][j] += xv * wv[j];
            }
        }
        __syncthreads();
    }

    // epilogue: demod scale + bias, write to g_y66[b][oc][m]
#pragma unroll
    for (int j = 0; j < 4; j++) {
        int oc = nblk * 64 + tn * 4 + j;
        float d  = g_demod[b * 512 + oc];
        float bs = cb[oc];
        float* dst = g_y66 + ((size_t)(b * 512 + oc)) * 4356;
#pragma unroll
        for (int i = 0; i < 8; i++) {
            int m = mbase + i;
            if (m < 4356) dst[m] = acc[i][j] * d + bs;
        }
    }
}

// ---------------- K7: fused filtered leaky-ReLU ----------------
// up x2 (12-tap separable, pad 9/8, gain 2 per axis) -> lrelu*sqrt2, clamp 256 -> down x2 (12-tap)
// One block per (32x32 output tile, channel, batch).
__global__ void __launch_bounds__(512) k_flrelu(const float* __restrict__ fu,
                                                const float* __restrict__ fd,
                                                float* __restrict__ out) {
    const int tile = blockIdx.x, ch = blockIdx.y, b = blockIdx.z;
    const int ox0 = (tile & 1) * 32, oy0 = (tile >> 1) * 32;
    const int tid = threadIdx.x;
    const int nthr = blockDim.x;

    __shared__ float sy[43][44];  // conv-out halo [oy0-4 .. oy0+38] x [ox0-4 .. ox0+38]
    __shared__ float sv[43][76];  // after horizontal up-filter (also reused for st[75][32])
    __shared__ float sz[75][76];  // after vertical up-filter + lrelu (z-grid)
    __shared__ float sfu[12], sfd[12];

    if (tid < 12) sfu[tid] = fu[tid] * 2.0f;          // gain 2 per axis (total 4)
    else if (tid < 24) sfd[tid - 12] = fd[tid - 12];

    const float* ysrc = g_y66 + ((size_t)(b * 512 + ch)) * 4356;
    for (int idx = tid; idx < 43 * 43; idx += nthr) {
        int r = idx / 43, c = idx % 43;
        int gy = oy0 - 4 + r, gx = ox0 - 4 + c;
        float v = 0.f;
        if ((unsigned)gy < 66u && (unsigned)gx < 66u) v = ysrc[gy * 66 + gx];
        sy[r][c] = v;
    }
    __syncthreads();

    // P1: horizontal up-filter.  z-col n = 2*ox0 + nx ; source col local = ((nx-8)>>1)+4+t
    for (int idx = tid; idx < 43 * 75; idx += nthr) {
        int r = idx / 75, nx = idx % 75;
        int base = ((nx - 8) >> 1) + 4;
        int tsel = (nx & 1) ? 0 : 1;  // n odd -> even taps f[2t]; n even -> odd taps f[2t+1]
        float a = 0.f;
#pragma unroll
        for (int t = 0; t < 6; t++) a += sfu[2 * t + tsel] * sy[r][base + t];
        sv[r][nx] = a;
    }
    __syncthreads();

    // P2: vertical up-filter + lrelu + clamp -> z
    for (int idx = tid; idx < 75 * 75; idx += nthr) {
        int my = idx / 75, nx = idx % 75;
        int base = ((my - 8) >> 1) + 4;
        int tsel = (my & 1) ? 0 : 1;
        float a = 0.f;
#pragma unroll
        for (int t = 0; t < 6; t++) a += sfu[2 * t + tsel] * sv[base + t][nx];
        a = (a < 0.f ? 0.2f * a : a) * 1.4142135623730951f;
        a = fminf(fmaxf(a, -256.f), 256.f);
        sz[my][nx] = a;
    }
    __syncthreads();

    // P3: horizontal down-filter (stride 2) -> st[75][32], reusing sv storage
    float* st = &sv[0][0];
    for (int idx = tid; idx < 75 * 32; idx += nthr) {
        int my = idx / 32, q = idx % 32;
        float a = 0.f;
#pragma unroll
        for (int k = 0; k < 12; k++) a += sfd[k] * sz[my][2 * q + k];
        st[my * 32 + q] = a;
    }
    __syncthreads();

    // P4: vertical down-filter (stride 2) + store
    for (int idx = tid; idx < 32 * 32; idx += nthr) {
        int p = idx / 32, q = idx % 32;
        float a = 0.f;
#pragma unroll
        for (int k = 0; k < 12; k++) a += sfd[k] * st[(2 * p + k) * 32 + q];
        out[(((size_t)(b * 512 + ch)) * 64 + (oy0 + p)) * 64 + (ox0 + q)] = a;
    }
}

// ---------------- launch ----------------
extern "C" void kernel_launch(void* const* d_in, const int* in_sizes, int n_in,
                              void* d_out, int out_size) {
    (void)in_sizes; (void)n_in; (void)out_size;
    const float* x    = (const float*)d_in[0];
    const float* w    = (const float*)d_in[1];
    const float* aw   = (const float*)d_in[2];
    const float* ab   = (const float*)d_in[3];
    const float* cw   = (const float*)d_in[4];
    const float* cb   = (const float*)d_in[5];
    const float* fu   = (const float*)d_in[6];
    const float* fd   = (const float*)d_in[7];
    const float* wavg = (const float*)d_in[8];
    float* out = (float*)d_out;

    k_reduce<<<2048, 256>>>(x, 8 * 512 * 64 * 64);
    k_finalize<<<1, 1024>>>(wavg, 1.0f / (8.f * 512.f * 64.f * 64.f));
    k_styles<<<16, 256>>>(w, aw, ab);
    k_S<<<1024, 256>>>(cw);
    k_demod<<<16, 256>>>();
    k_conv<<<dim3(35, 8, 8), 256>>>(x, cw, cb);
    k_flrelu<<<dim3(4, 512, 8), 512>>>(fu, fd, out);
}

// round 4
// speedup vs baseline: 4.5288x; 4.5288x over previous
#include <cuda_runtime.h>
#include <cuda_bf16.h>
#include <math.h>
#include <stdint.h>

#if defined(__CUDA_ARCH__) && defined(__CUDA_ARCH_FEAT_SM103_ALL)
#define HAS_TC 1
#else
#define HAS_TC 0
#endif

// ---------------- scratch ----------------
static __device__ float    g_y66[8 * 512 * 66 * 66];   // conv output 71.4 MB
static __device__ __align__(16) uint32_t g_xhl[8 * 512 * 64 * 64];   // packed (lo<<16|hi) bf16 split
static __device__ __align__(16) uint16_t g_bh[512 * 4608];           // weight hi bf16 (K-major)
static __device__ __align__(16) uint16_t g_bl[512 * 4608];           // weight lo bf16
static __device__ float g_partials[2048];
static __device__ float g_inv[1];
static __device__ float g_styles[8 * 512];
static __device__ float g_mult[8 * 512];
static __device__ float g_S[512 * 512];
static __device__ float g_demod[8 * 512];

// ---------------- PTX helpers ----------------
__device__ __forceinline__ uint32_t smem_u32(const void* p) {
    uint32_t a;
    asm("{ .reg .u64 t; cvta.to.shared.u64 t, %1; cvt.u32.u64 %0, t; }" : "=r"(a) : "l"(p));
    return a;
}
__device__ __forceinline__ uint32_t elect_one() {
    uint32_t p;
    asm volatile("{\n\t.reg .pred p;\n\telect.sync _|p, 0xFFFFFFFF;\n\tselp.b32 %0, 1, 0, p;\n\t}" : "=r"(p));
    return p;
}
#define MBAR_INIT(mb, c)  asm volatile("mbarrier.init.shared.b64 [%0], %1;" :: "r"(mb), "r"(c) : "memory")
#define FENCE_ASYNC()     asm volatile("fence.proxy.async.shared::cta;" ::: "memory")

__device__ __forceinline__ void mbar_wait(uint32_t mb, uint32_t parity) {
    uint32_t done;
    asm volatile("{\n\t.reg .pred p;\n\tmbarrier.try_wait.parity.acquire.cta.shared::cta.b64 p, [%1], %2;\n\tselp.b32 %0, 1, 0, p;\n\t}"
                 : "=r"(done) : "r"(mb), "r"(parity) : "memory");
    if (!done) {
        asm volatile("{\n\t.reg .pred P1;\n\tWL_%=:\n\tmbarrier.try_wait.parity.acquire.cta.shared::cta.b64 P1, [%0], %1, 0x989680;\n\t@P1 bra.uni WD_%=;\n\tbra.uni WL_%=;\n\tWD_%=:\n\t}"
                     :: "r"(mb), "r"(parity) : "memory");
    }
}

// packed fp32x2 FMA: d = a*b + d  (two fp32 lanes per instruction)
__device__ __forceinline__ void fma2(unsigned long long& d, unsigned long long a, unsigned long long b) {
    asm("fma.rn.f32x2 %0, %1, %2, %0;" : "+l"(d) : "l"(a), "l"(b));
}

#if HAS_TC
#define TC_ALLOC(sm, n)   asm volatile("tcgen05.alloc.cta_group::1.sync.aligned.shared::cta.b32 [%0], %1;" :: "r"(sm), "r"(n) : "memory")
#define TC_DEALLOC(t, n)  asm volatile("tcgen05.dealloc.cta_group::1.sync.aligned.b32 %0, %1;" :: "r"(t), "r"(n))
#define TC_RELINQ()       asm volatile("tcgen05.relinquish_alloc_permit.cta_group::1.sync.aligned;")
#define TC_COMMIT(mb)     asm volatile("tcgen05.commit.cta_group::1.mbarrier::arrive::one.shared::cluster.b64 [%0];" :: "r"(mb) : "memory")
#define TC_FENCE_AFTER()  asm volatile("tcgen05.fence::after_thread_sync;" ::: "memory")
#define TC_FENCE_BEFORE() asm volatile("tcgen05.fence::before_thread_sync;" ::: "memory")
#define TC_WAIT_LD()      asm volatile("tcgen05.wait::ld.sync.aligned;" ::: "memory")
__device__ __forceinline__ void mma_f16_ss(uint32_t d, uint64_t a, uint64_t b, uint32_t idesc, uint32_t en) {
    asm volatile("{\n\t.reg .pred p;\n\tsetp.ne.u32 p, %4, 0;\n\t"
                 "tcgen05.mma.cta_group::1.kind::f16 [%0], %1, %2, %3, {%5, %5, %5, %5}, p;\n\t}"
                 :: "r"(d), "l"(a), "l"(b), "r"(idesc), "r"(en), "r"(0u) : "memory");
}
#endif

// SW128 K-major descriptor base: layout=2, version=1, SBO=64, LBO=1
__device__ __forceinline__ uint64_t mk_desc(uint32_t addr) {
    return ((uint64_t)2 << 61) | ((uint64_t)1 << 46) | ((uint64_t)64 << 32) | ((uint64_t)1 << 16)
         | (uint64_t)((addr >> 4) & 0x3FFF);
}
// idesc kind::f16: F32 accum | A=BF16 | B=BF16 | N=256 | M=128
#define IDESC_M128_N256 ((1u<<4) | (1u<<7) | (1u<<10) | (32u<<17) | (8u<<24))

// ---------------- small prep kernels ----------------
__global__ void __launch_bounds__(256) k_reduce(const float* __restrict__ x, int n) {
    float s = 0.f;
    for (int i = blockIdx.x * blockDim.x + threadIdx.x; i < n; i += gridDim.x * blockDim.x) {
        float v = x[i]; s += v * v;
    }
    __shared__ float sm[256];
    sm[threadIdx.x] = s; __syncthreads();
    for (int o = 128; o > 0; o >>= 1) { if (threadIdx.x < o) sm[threadIdx.x] += sm[threadIdx.x + o]; __syncthreads(); }
    if (threadIdx.x == 0) g_partials[blockIdx.x] = sm[0];
}
__global__ void __launch_bounds__(1024) k_finalize(const float* __restrict__ w_avg, float inv_n) {
    __shared__ float sm[1024];
    float s = 0.f;
    for (int i = threadIdx.x; i < 2048; i += 1024) s += g_partials[i];
    sm[threadIdx.x] = s; __syncthreads();
    for (int o = 512; o > 0; o >>= 1) { if (threadIdx.x < o) sm[threadIdx.x] += sm[threadIdx.x + o]; __syncthreads(); }
    if (threadIdx.x == 0) {
        float mag = sm[0] * inv_n;
        float wn  = mag + 0.999f * (w_avg[0] - mag);
        g_inv[0]  = rsqrtf(wn);
    }
}
__global__ void __launch_bounds__(256) k_styles(const float* __restrict__ w, const float* __restrict__ aw,
                                                const float* __restrict__ ab) {
    int idx = blockIdx.x * 256 + threadIdx.x;
    int b = idx >> 9, i = idx & 511;
    const float* wr = w + b * 512;
    const float* ar = aw + i * 512;
    float s = 0.f;
    for (int j = 0; j < 512; j++) s += wr[j] * ar[j];
    s = s * 0.04419417382415922f + ab[i];
    g_styles[idx] = s;
    g_mult[idx]   = s * g_inv[0];
}
__global__ void __launch_bounds__(256) k_S(const float* __restrict__ cw) {
    int idx = blockIdx.x * 256 + threadIdx.x;
    const float* p = cw + (size_t)idx * 9;
    float s = 0.f;
#pragma unroll
    for (int k = 0; k < 9; k++) s += p[k] * p[k];
    g_S[idx] = s;
}
__global__ void __launch_bounds__(256) k_demod() {
    int idx = blockIdx.x * 256 + threadIdx.x;
    int b = idx >> 9, o = idx & 511;
    const float* st = g_styles + b * 512;
    const float* Sr = g_S + o * 512;
    float s = 0.f;
    for (int i = 0; i < 512; i++) { float t = st[i]; s += t * t * Sr[i]; }
    g_demod[idx] = rsqrtf(s + 1e-8f);
}
__global__ void __launch_bounds__(256) k_split_x(const float* __restrict__ x) {
    int i = blockIdx.x * 256 + threadIdx.x;
    float v = x[i] * g_mult[i >> 12];
    __nv_bfloat16 h = __float2bfloat16(v);
    float hf = __bfloat162float(h);
    __nv_bfloat16 l = __float2bfloat16(v - hf);
    g_xhl[i] = ((uint32_t)__bfloat16_as_ushort(l) << 16) | (uint32_t)__bfloat16_as_ushort(h);
}
__global__ void __launch_bounds__(256) k_pack_B(const float* __restrict__ cw) {
    int i = blockIdx.x * 256 + threadIdx.x;
    float v = cw[i];
    __nv_bfloat16 h = __float2bfloat16(v);
    float hf = __bfloat162float(h);
    __nv_bfloat16 l = __float2bfloat16(v - hf);
    g_bh[i] = __bfloat16_as_ushort(h);
    g_bl[i] = __bfloat16_as_ushort(l);
}

// ================= conv path A: tcgen05 (sm_103a codegen only) =================
// CTA: M=256 px (2 x M128 atoms) x N=256 oc, K=4608 in 72 chunks of 64.
#define CONV_SMEM (128 * 1024 + 1024)

__global__ void __launch_bounds__(256, 1) k_conv_tc(const float* __restrict__ cb) {
#if HAS_TC
    extern __shared__ char dsm[];
    __shared__ uint32_t s_tmem[1];
    __shared__ __align__(8) unsigned long long s_mbar[1];
    __shared__ float s_d[256], s_b[256];

    const int tid = threadIdx.x;
    const int wid = tid >> 5, lid = tid & 31;
    const int mpair = blockIdx.x;
    const int n0 = blockIdx.y * 256;
    const int b = blockIdx.z;
    const int m0 = mpair * 256;

    const uint32_t dsm0 = smem_u32(dsm);
    uint32_t base = (dsm0 + 1023) & ~1023u;
    const uint32_t sAh = base, sAl = base + 32768, sBh = base + 65536, sBl = base + 98304;
    char* const pbase = dsm + (base - dsm0);
    uint32_t mbar = smem_u32(s_mbar);

    if (wid == 0) { TC_ALLOC(smem_u32(s_tmem), 512); TC_RELINQ(); }
    if (tid == 0) MBAR_INIT(mbar, 1);
    __syncthreads();
    const uint32_t tmem = s_tmem[0];

    const int gpix = m0 + tid;
    const int r = gpix / 66, c = gpix % 66;
    const uint32_t* xb = g_xhl + ((size_t)b << 21);
    const uint32_t arow = (uint32_t)((tid >> 3) << 10) + (uint32_t)((tid & 7) << 7);

    const uint64_t dAh = mk_desc(sAh), dAl = mk_desc(sAl), dBh = mk_desc(sBh), dBl = mk_desc(sBl);

    uint32_t parity = 0;
    for (int kc = 0; kc < 72; kc++) {
        const int k0 = kc * 64;
        if (kc > 0) { mbar_wait(mbar, parity); parity ^= 1; }

        // ---- B tiles: 256 oc rows x 64 k, hi+lo, SW128 ----
        {
            const char* ph = (const char*)g_bh + (size_t)n0 * 9216 + (size_t)k0 * 2;
            const char* pl = (const char*)g_bl + (size_t)n0 * 9216 + (size_t)k0 * 2;
#pragma unroll
            for (int it = 0; it < 8; it++) {
                int i = it * 256 + tid;
                int row = i >> 3, seg = i & 7;
                const int4 vh = *(const int4*)(ph + (size_t)row * 9216 + seg * 16);
                const int4 vl = *(const int4*)(pl + (size_t)row * 9216 + seg * 16);
                uint32_t off = (uint32_t)((row >> 3) << 10) + (uint32_t)((row & 7) << 7) + (uint32_t)(seg << 4);
                uint32_t sw = off ^ ((off >> 3) & 0x70);
                *(int4*)(pbase + (sBh - base) + sw) = vh;
                *(int4*)(pbase + (sBl - base) + sw) = vl;
            }
        }
        // ---- A tiles: im2col 256 px x 64 k, hi+lo, SW128 ----
        {
            int ic = k0 / 9, pos = k0 - ic * 9;
#pragma unroll 8
            for (int kk = 0; kk < 64; kk += 2) {
                int kh0 = (pos >= 6) ? 2 : ((pos >= 3) ? 1 : 0);
                int kw0 = pos - kh0 * 3;
                int gr0 = r + kh0 - 2, gc0 = c + kw0 - 2;
                uint32_t v0 = 0;
                if ((unsigned)gr0 < 64u && (unsigned)gc0 < 64u) v0 = xb[(ic << 12) + (gr0 << 6) + gc0];
                pos++; if (pos == 9) { pos = 0; ic++; }
                int kh1 = (pos >= 6) ? 2 : ((pos >= 3) ? 1 : 0);
                int kw1 = pos - kh1 * 3;
                int gr1 = r + kh1 - 2, gc1 = c + kw1 - 2;
                uint32_t v1 = 0;
                if ((unsigned)gr1 < 64u && (unsigned)gc1 < 64u) v1 = xb[(ic << 12) + (gr1 << 6) + gc1];
                pos++; if (pos == 9) { pos = 0; ic++; }
                uint32_t hi = __byte_perm(v0, v1, 0x5410);
                uint32_t lo = __byte_perm(v0, v1, 0x7632);
                uint32_t off = arow + (uint32_t)(kk << 1);
                uint32_t sw = off ^ ((off >> 3) & 0x70);
                *(uint32_t*)(pbase + (sAh - base) + sw) = hi;
                *(uint32_t*)(pbase + (sAl - base) + sw) = lo;
            }
        }
        FENCE_ASYNC();
        __syncthreads();

        if (wid == 0 && elect_one()) {
#pragma unroll
            for (int ks = 0; ks < 4; ks++) {
                uint32_t en = (kc > 0 || ks > 0) ? 1u : 0u;
                uint64_t koff = (uint64_t)(ks * 2);
                mma_f16_ss(tmem + 0,   dAh + koff,        dBh + koff, IDESC_M128_N256, en);
                mma_f16_ss(tmem + 256, dAh + 1024 + koff, dBh + koff, IDESC_M128_N256, en);
                mma_f16_ss(tmem + 0,   dAh + koff,        dBl + koff, IDESC_M128_N256, 1u);
                mma_f16_ss(tmem + 256, dAh + 1024 + koff, dBl + koff, IDESC_M128_N256, 1u);
                mma_f16_ss(tmem + 0,   dAl + koff,        dBh + koff, IDESC_M128_N256, 1u);
                mma_f16_ss(tmem + 256, dAl + 1024 + koff, dBh + koff, IDESC_M128_N256, 1u);
            }
            TC_COMMIT(mbar);
        }
    }
    mbar_wait(mbar, parity);
    TC_FENCE_AFTER();

    s_d[tid] = g_demod[b * 512 + n0 + tid];
    s_b[tid] = cb[n0 + tid];
    __syncthreads();

    const int atom = wid >> 2;
    const int sub = wid & 3;
    const int mrow = atom * 128 + sub * 32 + lid;
    const int opix = m0 + mrow;
    float* dst = g_y66 + ((size_t)(b * 512 + n0)) * 4356 + opix;
    const uint32_t tbase = tmem + ((uint32_t)sub << 21) + (uint32_t)atom * 256;

    for (int c0 = 0; c0 < 256; c0 += 32) {
        uint32_t rg[32];
        asm volatile("tcgen05.ld.sync.aligned.32x32b.x32.b32 "
            "{%0,%1,%2,%3,%4,%5,%6,%7,%8,%9,%10,%11,%12,%13,%14,%15,"
            "%16,%17,%18,%19,%20,%21,%22,%23,%24,%25,%26,%27,%28,%29,%30,%31}, [%32];"
            : "=r"(rg[0]), "=r"(rg[1]), "=r"(rg[2]), "=r"(rg[3]), "=r"(rg[4]), "=r"(rg[5]), "=r"(rg[6]), "=r"(rg[7]),
              "=r"(rg[8]), "=r"(rg[9]), "=r"(rg[10]), "=r"(rg[11]), "=r"(rg[12]), "=r"(rg[13]), "=r"(rg[14]), "=r"(rg[15]),
              "=r"(rg[16]), "=r"(rg[17]), "=r"(rg[18]), "=r"(rg[19]), "=r"(rg[20]), "=r"(rg[21]), "=r"(rg[22]), "=r"(rg[23]),
              "=r"(rg[24]), "=r"(rg[25]), "=r"(rg[26]), "=r"(rg[27]), "=r"(rg[28]), "=r"(rg[29]), "=r"(rg[30]), "=r"(rg[31])
            : "r"(tbase + c0));
        TC_WAIT_LD();
        if (opix < 4356) {
#pragma unroll
            for (int j = 0; j < 32; j++) {
                int n = c0 + j;
                dst[(size_t)n * 4356] = __uint_as_float(rg[j]) * s_d[n] + s_b[n];
            }
        }
    }
    TC_FENCE_BEFORE();
    __syncthreads();
    if (wid == 0) TC_DEALLOC(tmem, 512);
#endif
}

// ================= conv path B: packed fp32x2 fallback =================
// Block tile 128 M x 64 N, 256 threads, thread = 4 M-pairs x 4 N (FFMA2 along M).
__global__ void __launch_bounds__(256) k_conv_f32x2(const float* __restrict__ x,
                                                    const float* __restrict__ cw,
                                                    const float* __restrict__ cb) {
#if !HAS_TC
    const int mblk = blockIdx.x, nblk = blockIdx.y, b = blockIdx.z;
    const int tid = threadIdx.x;
    const int tn = tid & 15;
    const int tm = tid >> 4;
    const int m0 = mblk * 128;
    const int row0 = m0 / 66;

    __shared__ __align__(8) float xsA[5][68];            // xs flat
    __shared__ __align__(8) float xsB[5][68];            // xs shifted by one float
    __shared__ unsigned long long ws2[9][64];            // (w,w) duplicated

    const int mbase = m0 + tm * 8;                       // even
    int rrp[4], qqp[4];
#pragma unroll
    for (int p = 0; p < 4; p++) {
        int m = mbase + 2 * p;
        rrp[p] = m / 66 - row0;   // 0..2
        qqp[p] = m % 66;          // even
    }

    unsigned long long acc[4][4];
#pragma unroll
    for (int p = 0; p < 4; p++)
#pragma unroll
        for (int j = 0; j < 4; j++) acc[p][j] = 0ull;

    const float* xb = x + (size_t)b * 512 * 4096;
    const float* mb = g_mult + b * 512;

    for (int ic = 0; ic < 512; ++ic) {
        const float mlt = __ldg(mb + ic);
        for (int idx = tid; idx < 340; idx += 256) {
            int sr = idx / 68, s = idx % 68;
            int gr = row0 + sr - 2, gc = s - 2;
            float v = 0.f;
            if ((unsigned)gr < 64u && (unsigned)gc < 64u)
                v = xb[ic * 4096 + gr * 64 + gc] * mlt;
            xsA[sr][s] = v;
            if (s) xsB[sr][s - 1] = v;
        }
        for (int idx = tid; idx < 576; idx += 256) {
            int oc = idx / 9, pos = idx % 9;
            uint32_t wv = __float_as_uint(cw[((size_t)(nblk * 64 + oc) * 512 + ic) * 9 + pos]);
            ws2[pos][oc] = (unsigned long long)wv | ((unsigned long long)wv << 32);
        }
        __syncthreads();
#pragma unroll
        for (int pos = 0; pos < 9; ++pos) {
            const int kh = pos / 3, kw = pos % 3;
            unsigned long long wv[4];
#pragma unroll
            for (int j = 0; j < 4; j++) wv[j] = ws2[pos][tn * 4 + j];
#pragma unroll
            for (int p = 0; p < 4; p++) {
                int rw = rrp[p] + kh;
                int s = qqp[p] + kw;
                unsigned long long xv = (kw & 1)
                    ? *(const unsigned long long*)&xsB[rw][s - 1]
                    : *(const unsigned long long*)&xsA[rw][s];
#pragma unroll
                for (int j = 0; j < 4; j++) fma2(acc[p][j], xv, wv[j]);
            }
        }
        __syncthreads();
    }

#pragma unroll
    for (int j = 0; j < 4; j++) {
        int oc = nblk * 64 + tn * 4 + j;
        float d  = g_demod[b * 512 + oc];
        float bs = cb[oc];
        float* dst = g_y66 + ((size_t)(b * 512 + oc)) * 4356;
#pragma unroll
        for (int p = 0; p < 4; p++) {
            unsigned long long a = acc[p][j];
            float lo = __uint_as_float((uint32_t)a);
            float hi = __uint_as_float((uint32_t)(a >> 32));
            int m = mbase + 2 * p;
            if (m < 4356)     dst[m]     = lo * d + bs;
            if (m + 1 < 4356) dst[m + 1] = hi * d + bs;
        }
    }
#endif
}

// ---------------- fused filtered leaky-ReLU ----------------
__global__ void __launch_bounds__(512) k_flrelu(const float* __restrict__ fu,
                                                const float* __restrict__ fd,
                                                float* __restrict__ out) {
    const int tile = blockIdx.x, ch = blockIdx.y, b = blockIdx.z;
    const int ox0 = (tile & 1) * 32, oy0 = (tile >> 1) * 32;
    const int tid = threadIdx.x;
    const int nthr = blockDim.x;

    __shared__ float sy[43][44];
    __shared__ float sv[43][76];
    __shared__ float sz[75][76];
    __shared__ float sfu[12], sfd[12];

    if (tid < 12) sfu[tid] = fu[tid] * 2.0f;
    else if (tid < 24) sfd[tid - 12] = fd[tid - 12];

    const float* ysrc = g_y66 + ((size_t)(b * 512 + ch)) * 4356;
    for (int idx = tid; idx < 43 * 43; idx += nthr) {
        int r = idx / 43, c = idx % 43;
        int gy = oy0 - 4 + r, gx = ox0 - 4 + c;
        float v = 0.f;
        if ((unsigned)gy < 66u && (unsigned)gx < 66u) v = ysrc[gy * 66 + gx];
        sy[r][c] = v;
    }
    __syncthreads();

    for (int idx = tid; idx < 43 * 75; idx += nthr) {
        int r = idx / 75, nx = idx % 75;
        int base = ((nx - 8) >> 1) + 4;
        int tsel = (nx & 1) ? 0 : 1;
        float a = 0.f;
#pragma unroll
        for (int t = 0; t < 6; t++) a += sfu[2 * t + tsel] * sy[r][base + t];
        sv[r][nx] = a;
    }
    __syncthreads();

    for (int idx = tid; idx < 75 * 75; idx += nthr) {
        int my = idx / 75, nx = idx % 75;
        int base = ((my - 8) >> 1) + 4;
        int tsel = (my & 1) ? 0 : 1;
        float a = 0.f;
#pragma unroll
        for (int t = 0; t < 6; t++) a += sfu[2 * t + tsel] * sv[base + t][nx];
        a = (a < 0.f ? 0.2f * a : a) * 1.4142135623730951f;
        a = fminf(fmaxf(a, -256.f), 256.f);
        sz[my][nx] = a;
    }
    __syncthreads();

    float* st = &sv[0][0];
    for (int idx = tid; idx < 75 * 32; idx += nthr) {
        int my = idx / 32, q = idx % 32;
        float a = 0.f;
#pragma unroll
        for (int k = 0; k < 12; k++) a += sfd[k] * sz[my][2 * q + k];
        st[my * 32 + q] = a;
    }
    __syncthreads();

    for (int idx = tid; idx < 32 * 32; idx += nthr) {
        int p = idx / 32, q = idx % 32;
        float a = 0.f;
#pragma unroll
        for (int k = 0; k < 12; k++) a += sfd[k] * st[(2 * p + k) * 32 + q];
        out[(((size_t)(b * 512 + ch)) * 64 + (oy0 + p)) * 64 + (ox0 + q)] = a;
    }
}

// ---------------- launch ----------------
extern "C" void kernel_launch(void* const* d_in, const int* in_sizes, int n_in,
                              void* d_out, int out_size) {
    (void)in_sizes; (void)n_in; (void)out_size;
    const float* x    = (const float*)d_in[0];
    const float* w    = (const float*)d_in[1];
    const float* aw   = (const float*)d_in[2];
    const float* ab   = (const float*)d_in[3];
    const float* cw   = (const float*)d_in[4];
    const float* cb   = (const float*)d_in[5];
    const float* fu   = (const float*)d_in[6];
    const float* fd   = (const float*)d_in[7];
    const float* wavg = (const float*)d_in[8];
    float* out = (float*)d_out;

    cudaFuncSetAttribute(k_conv_tc, cudaFuncAttributeMaxDynamicSharedMemorySize, CONV_SMEM);

    k_reduce<<<2048, 256>>>(x, 8 * 512 * 64 * 64);
    k_finalize<<<1, 1024>>>(wavg, 1.0f / (8.f * 512.f * 64.f * 64.f));
    k_styles<<<16, 256>>>(w, aw, ab);
    k_S<<<1024, 256>>>(cw);
    k_demod<<<16, 256>>>();
    k_split_x<<<65536, 256>>>(x);
    k_pack_B<<<9216, 256>>>(cw);
    // exactly one of these two has a non-empty body per compiled arch:
    k_conv_tc<<<dim3(18, 2, 8), 256, CONV_SMEM>>>(cb);
    k_conv_f32x2<<<dim3(35, 8, 8), 256>>>(x, cw, cb);
    k_flrelu<<<dim3(4, 512, 8), 512>>>(fu, fd, out);
}